// round 1
// baseline (speedup 1.0000x reference)
#include <cuda_runtime.h>

// DyDepthwiseConvAtten: B=1024, N=100, C=256, K=3
// Per row (b,n):
//   w[k]   = sum_c q[c] * W_w[k,c] + b_w[k]           (k = 0..2)
//   out[c] = v[c-1]*w[0] + v[c]*w[1] + v[c+1]*w[2]    (zero-pad boundaries)
//   out    = LayerNorm_C(out) * gamma + beta
//
// One 256-thread CTA per row; thread t owns channel t. Each global element
// read/written exactly once, coalesced. HBM-bound: ~315MB traffic.

#define C_DIM 256
#define LN_EPS 1e-5f

__global__ __launch_bounds__(C_DIM, 8)
void dydw_atten_kernel(const float* __restrict__ q,
                       const float* __restrict__ v,
                       const float* __restrict__ Ww,   // [3, 256]
                       const float* __restrict__ bw,   // [3]
                       const float* __restrict__ gamma,
                       const float* __restrict__ beta,
                       float* __restrict__ out) {
    const int row  = blockIdx.x;            // 0 .. B*N-1
    const int c    = threadIdx.x;           // 0 .. 255
    const int warp = c >> 5;
    const int lane = c & 31;

    const size_t base = (size_t)row * C_DIM;

    __shared__ float sv[C_DIM + 2];         // padded value row
    __shared__ float red[8][3];             // cross-warp partials for w[k]
    __shared__ float red2[8][2];            // cross-warp partials for LN
    __shared__ float s_w[3];
    __shared__ float s_mu, s_rstd;

    // ---- load row (one float each, coalesced) ----
    const float qv = q[base + c];
    const float vv = v[base + c];
    sv[c + 1] = vv;
    if (c == 0)       sv[0]         = 0.0f;
    if (c == C_DIM-1) sv[C_DIM + 1] = 0.0f;

    // ---- dynamic weights: 3 dot products over C, fused reduction ----
    float p0 = qv * Ww[c];
    float p1 = qv * Ww[C_DIM + c];
    float p2 = qv * Ww[2*C_DIM + c];
    #pragma unroll
    for (int off = 16; off > 0; off >>= 1) {
        p0 += __shfl_down_sync(0xffffffffu, p0, off);
        p1 += __shfl_down_sync(0xffffffffu, p1, off);
        p2 += __shfl_down_sync(0xffffffffu, p2, off);
    }
    if (lane == 0) { red[warp][0] = p0; red[warp][1] = p1; red[warp][2] = p2; }
    __syncthreads();

    if (c < 3) {
        float s = 0.0f;
        #pragma unroll
        for (int w8 = 0; w8 < 8; w8++) s += red[w8][c];
        s_w[c] = s + bw[c];
    }
    __syncthreads();

    const float w0 = s_w[0], w1 = s_w[1], w2 = s_w[2];

    // ---- depthwise conv along C (cross-correlation, 'same' padding) ----
    const float o = sv[c] * w0 + sv[c + 1] * w1 + sv[c + 2] * w2;

    // ---- LayerNorm over C: fused sum + sumsq reduction ----
    float s1 = o, s2 = o * o;
    #pragma unroll
    for (int off = 16; off > 0; off >>= 1) {
        s1 += __shfl_down_sync(0xffffffffu, s1, off);
        s2 += __shfl_down_sync(0xffffffffu, s2, off);
    }
    if (lane == 0) { red2[warp][0] = s1; red2[warp][1] = s2; }
    __syncthreads();

    if (c == 0) {
        float t1 = 0.0f, t2 = 0.0f;
        #pragma unroll
        for (int w8 = 0; w8 < 8; w8++) { t1 += red2[w8][0]; t2 += red2[w8][1]; }
        const float mu  = t1 * (1.0f / C_DIM);
        const float var = t2 * (1.0f / C_DIM) - mu * mu;
        s_mu   = mu;
        s_rstd = rsqrtf(var + LN_EPS);
    }
    __syncthreads();

    out[base + c] = (o - s_mu) * s_rstd * gamma[c] + beta[c];
}

extern "C" void kernel_launch(void* const* d_in, const int* in_sizes, int n_in,
                              void* d_out, int out_size) {
    const float* q     = (const float*)d_in[0];
    const float* v     = (const float*)d_in[1];
    const float* Ww    = (const float*)d_in[2];
    const float* bw    = (const float*)d_in[3];
    const float* gamma = (const float*)d_in[4];
    const float* beta  = (const float*)d_in[5];
    float* out = (float*)d_out;

    const int rows = out_size / C_DIM;      // B*N = 102400
    dydw_atten_kernel<<<rows, C_DIM>>>(q, v, Ww, bw, gamma, beta, out);
}

// round 2
// speedup vs baseline: 2.4930x; 2.4930x over previous
#include <cuda_runtime.h>

// DyDepthwiseConvAtten: B=1024, N=100, C=256, K=3  (rows = 102400)
// Round 2: one WARP per row, 8 channels/thread, float4 loads/stores,
// all reductions via shfl.xor butterflies. No shared memory, no barriers.

#define C_DIM 256
#define LN_EPS 1e-5f
#define ROWS_PER_CTA 8          // 8 warps * 32 threads = 256 threads/CTA

__global__ __launch_bounds__(ROWS_PER_CTA * 32, 8)
void dydw_atten_kernel(const float* __restrict__ q,
                       const float* __restrict__ v,
                       const float* __restrict__ Ww,   // [3,256]
                       const float* __restrict__ bw,   // [3]
                       const float* __restrict__ gamma,
                       const float* __restrict__ beta,
                       float* __restrict__ out) {
    const int lane = threadIdx.x & 31;
    const int wrp  = threadIdx.x >> 5;
    const int row  = blockIdx.x * ROWS_PER_CTA + wrp;   // 0 .. 102399

    const size_t base = (size_t)row * C_DIM + lane * 8; // this thread's 8 channels
    const int    coff = lane * 8;                       // channel offset (weights)

    // ---- vector loads: 2x float4 of q and v each (front-batched for MLP) ----
    const float4 q0 = *(const float4*)(q + base);
    const float4 q1 = *(const float4*)(q + base + 4);
    const float4 v0 = *(const float4*)(v + base);
    const float4 v1 = *(const float4*)(v + base + 4);

    const float4 w00 = *(const float4*)(Ww + coff);
    const float4 w01 = *(const float4*)(Ww + coff + 4);
    const float4 w10 = *(const float4*)(Ww + C_DIM + coff);
    const float4 w11 = *(const float4*)(Ww + C_DIM + coff + 4);
    const float4 w20 = *(const float4*)(Ww + 2 * C_DIM + coff);
    const float4 w21 = *(const float4*)(Ww + 2 * C_DIM + coff + 4);

    // ---- dynamic weights: 3 dot products over C, warp butterfly reduce ----
    float p0 = q0.x*w00.x + q0.y*w00.y + q0.z*w00.z + q0.w*w00.w
             + q1.x*w01.x + q1.y*w01.y + q1.z*w01.z + q1.w*w01.w;
    float p1 = q0.x*w10.x + q0.y*w10.y + q0.z*w10.z + q0.w*w10.w
             + q1.x*w11.x + q1.y*w11.y + q1.z*w11.z + q1.w*w11.w;
    float p2 = q0.x*w20.x + q0.y*w20.y + q0.z*w20.z + q0.w*w20.w
             + q1.x*w21.x + q1.y*w21.y + q1.z*w21.z + q1.w*w21.w;
    #pragma unroll
    for (int off = 16; off > 0; off >>= 1) {
        p0 += __shfl_xor_sync(0xffffffffu, p0, off);
        p1 += __shfl_xor_sync(0xffffffffu, p1, off);
        p2 += __shfl_xor_sync(0xffffffffu, p2, off);
    }
    const float kw0 = p0 + bw[0];
    const float kw1 = p1 + bw[1];
    const float kw2 = p2 + bw[2];

    // ---- conv halos from neighbor lanes (zero-pad at row edges) ----
    float left  = __shfl_up_sync  (0xffffffffu, v1.w, 1);  // v[8t-1]
    float right = __shfl_down_sync(0xffffffffu, v0.x, 1);  // v[8t+8]
    if (lane == 0)  left  = 0.0f;
    if (lane == 31) right = 0.0f;

    // window vv[0..9] = v[8t-1 .. 8t+8]
    float vv[10];
    vv[0]=left;  vv[1]=v0.x; vv[2]=v0.y; vv[3]=v0.z; vv[4]=v0.w;
    vv[5]=v1.x;  vv[6]=v1.y; vv[7]=v1.z; vv[8]=v1.w; vv[9]=right;

    float o[8];
    #pragma unroll
    for (int i = 0; i < 8; i++)
        o[i] = vv[i]*kw0 + vv[i+1]*kw1 + vv[i+2]*kw2;

    // ---- LayerNorm: fused sum + sumsq warp butterflies ----
    float s1 = 0.0f, s2 = 0.0f;
    #pragma unroll
    for (int i = 0; i < 8; i++) { s1 += o[i]; s2 += o[i]*o[i]; }
    #pragma unroll
    for (int off = 16; off > 0; off >>= 1) {
        s1 += __shfl_xor_sync(0xffffffffu, s1, off);
        s2 += __shfl_xor_sync(0xffffffffu, s2, off);
    }
    const float mu   = s1 * (1.0f / C_DIM);
    const float var  = s2 * (1.0f / C_DIM) - mu * mu;
    const float rstd = rsqrtf(var + LN_EPS);

    const float4 g0 = *(const float4*)(gamma + coff);
    const float4 g1 = *(const float4*)(gamma + coff + 4);
    const float4 b0 = *(const float4*)(beta  + coff);
    const float4 b1 = *(const float4*)(beta  + coff + 4);

    float4 r0, r1;
    r0.x = (o[0]-mu)*rstd*g0.x + b0.x;
    r0.y = (o[1]-mu)*rstd*g0.y + b0.y;
    r0.z = (o[2]-mu)*rstd*g0.z + b0.z;
    r0.w = (o[3]-mu)*rstd*g0.w + b0.w;
    r1.x = (o[4]-mu)*rstd*g1.x + b1.x;
    r1.y = (o[5]-mu)*rstd*g1.y + b1.y;
    r1.z = (o[6]-mu)*rstd*g1.z + b1.z;
    r1.w = (o[7]-mu)*rstd*g1.w + b1.w;

    *(float4*)(out + base)     = r0;
    *(float4*)(out + base + 4) = r1;
}

extern "C" void kernel_launch(void* const* d_in, const int* in_sizes, int n_in,
                              void* d_out, int out_size) {
    const float* q     = (const float*)d_in[0];
    const float* v     = (const float*)d_in[1];
    const float* Ww    = (const float*)d_in[2];
    const float* bw    = (const float*)d_in[3];
    const float* gamma = (const float*)d_in[4];
    const float* beta  = (const float*)d_in[5];
    float* out = (float*)d_out;

    const int rows = out_size / C_DIM;                 // 102400
    dydw_atten_kernel<<<rows / ROWS_PER_CTA, ROWS_PER_CTA * 32>>>(
        q, v, Ww, bw, gamma, beta, out);
}